// round 4
// baseline (speedup 1.0000x reference)
#include <cuda_runtime.h>
#include <cuda_bf16.h>
#include <math.h>

#define BB 64
#define CC 80
#define DE 300
#define DE1 1024
#define JJ 4000
#define SS 100
#define KK 40
#define FDIM 2048

typedef unsigned long long ull;

// ---------------- scratch ----------------
__device__ float g_feat[BB * FDIM];
__device__ float g_b1t[CC * DE1];
__device__ float g_b2t[CC * DE1];
__device__ float g_Awave[CC * CC];
__device__ float g_Ahat[CC * CC];
__device__ float g_t1[CC * DE1];
__device__ float g_h[CC * DE1];
__device__ float g_y[CC * FDIM];
__device__ float g_x[CC * FDIM];
__device__ float g_img[BB * JJ];
__device__ float g_cls[CC * JJ];
__device__ float g_pooled[BB * CC * KK];
__device__ float g_slab[8 * BB * JJ];   // split-K partials, 8.19 MB

// ---------------- f32x2 helpers ----------------
__device__ __forceinline__ ull pack2(float lo, float hi) {
    ull r; asm("mov.b64 %0, {%1,%2};" : "=l"(r) : "f"(lo), "f"(hi)); return r;
}
__device__ __forceinline__ void unpack2(ull v, float& lo, float& hi) {
    asm("mov.b64 {%0,%1}, %2;" : "=f"(lo), "=f"(hi) : "l"(v));
}
__device__ __forceinline__ ull ffma2(ull a, ull b, ull c) {
    ull d; asm("fma.rn.f32x2 %0, %1, %2, %3;" : "=l"(d) : "l"(a), "l"(b), "l"(c)); return d;
}

// ---------------- small kernels ----------------

__global__ void k_maxpool(const float* __restrict__ f) {
    int warp = (blockIdx.x * blockDim.x + threadIdx.x) >> 5;
    int lane = threadIdx.x & 31;
    if (warp >= BB * FDIM) return;
    const float4* p = (const float4*)(f + (size_t)warp * 196);  // 49 aligned float4
    float m = -INFINITY;
    for (int i = lane; i < 49; i += 32) {
        float4 v = p[i];
        m = fmaxf(m, fmaxf(fmaxf(v.x, v.y), fmaxf(v.z, v.w)));
    }
    #pragma unroll
    for (int o = 16; o; o >>= 1) m = fmaxf(m, __shfl_xor_sync(0xffffffffu, m, o));
    if (lane == 0) g_feat[warp] = m;
}

__global__ void k_b1b2(const float* __restrict__ Wb1, const float* __restrict__ bb1,
                       const float* __restrict__ Wb2, const float* __restrict__ bb2,
                       const float* __restrict__ inp) {
    int idx = blockIdx.x * blockDim.x + threadIdx.x;
    if (idx >= 2 * DE1 * CC) return;
    int which = idx / (DE1 * CC);
    int r = idx % (DE1 * CC);
    int i = r / CC, c = r % CC;
    const float* W = which ? Wb2 : Wb1;
    const float* bv = which ? bb2 : bb1;
    float s = bv[i];
    #pragma unroll 4
    for (int d = 0; d < DE; d++) s = fmaf(W[i * DE + d], inp[d * CC + c], s);
    s = 1.0f / (1.0f + expf(-s));
    (which ? g_b2t : g_b1t)[c * DE1 + i] = s;
}

__global__ void k_awave() {
    int w = (blockIdx.x * blockDim.x + threadIdx.x) >> 5;
    int lane = threadIdx.x & 31;
    if (w >= CC * CC) return;
    int i = w / CC, j = w % CC;
    const float* p1 = g_b1t + (size_t)i * DE1;
    const float* p2 = g_b2t + (size_t)j * DE1;
    float s = 0.f;
    #pragma unroll 8
    for (int k = lane; k < DE1; k += 32) s = fmaf(p1[k], p2[k], s);
    #pragma unroll
    for (int o = 16; o; o >>= 1) s += __shfl_xor_sync(0xffffffffu, s, o);
    if (lane == 0) g_Awave[w] = s * (1.0f / CC) + (i == j ? 1.0f : 0.0f);
}

__global__ void k_norm(float* __restrict__ out_loss) {
    __shared__ float red[CC][8];
    __shared__ float dsh[CC];
    __shared__ float lred[1024];
    int t = threadIdx.x;
    if (t < CC * 8) {
        int i = t >> 3, p = t & 7;
        float s = 0.f;
        #pragma unroll
        for (int j = p * 10; j < p * 10 + 10; j++) s += g_Awave[i * CC + j];
        red[i][p] = s;
    }
    __syncthreads();
    if (t < CC) {
        float s = 0.f;
        #pragma unroll
        for (int p = 0; p < 8; p++) s += red[t][p];
        float d = rsqrtf(s);
        if (!isfinite(d)) d = 0.f;
        dsh[t] = d;
    }
    __syncthreads();
    float ls = 0.f;
    for (int idx = t; idx < CC * CC; idx += 1024) {
        int i = idx / CC, j = idx % CC;
        float v = dsh[i] * g_Awave[idx] * dsh[j];
        g_Ahat[idx] = v;
        ls += fabsf(v - (i == j ? 1.0f : 0.0f));
    }
    lred[t] = ls;
    __syncthreads();
    for (int o = 512; o; o >>= 1) {
        if (t < o) lred[t] += lred[t + o];
        __syncthreads();
    }
    if (t == 0 && out_loss) *out_loss = lred[0];
}

__global__ void k_gcn1() {
    int idx = blockIdx.x * blockDim.x + threadIdx.x;
    if (idx >= CC * DE1) return;
    int i = idx / DE1, j = idx % DE1;
    float s = 0.f;
    #pragma unroll 8
    for (int k = 0; k < CC; k++) s = fmaf(g_Ahat[i * CC + k], g_t1[k * DE1 + j], s);
    g_h[idx] = s > 0.f ? s : 0.2f * s;
}

__global__ void k_gcn2() {
    int idx = blockIdx.x * blockDim.x + threadIdx.x;
    if (idx >= CC * FDIM) return;
    int i = idx / FDIM, j = idx % FDIM;
    float s = 0.f;
    #pragma unroll 8
    for (int k = 0; k < CC; k++) s = fmaf(g_Ahat[i * CC + k], g_y[k * FDIM + j], s);
    g_x[idx] = s;
}

// ---------------- pipelined FFMA2 GEMM ----------------
// C = A[M,K] @ op(B); TRANSB: B[N,K] (A@B^T), else B[K,N] (A@B)
// BM=64, BN=128, BK=16, 256 threads, 4x8 outputs/thread (f32x2 accumulators)
// double-buffered smem + register prefetch; one __syncthreads per k-step.
// gridDim.z==1 -> write dst (+bias); else write slab[z].
template <bool TRANSB>
__global__ void __launch_bounds__(256, 2)
gemm_pl(const float* __restrict__ A, const float* __restrict__ B,
        float* __restrict__ slab, float* __restrict__ dst,
        const float* __restrict__ bias,
        int M, int N, int K, int kchunk) {
    __shared__ float As[2][16][68];   // 272B rows: 16B-aligned
    __shared__ float Bs[2][16][132];  // 528B rows: 16B-aligned
    const int tid = threadIdx.x;
    const int tx = tid & 15;    // col group *8
    const int ty = tid >> 4;    // row group *4
    const int m0 = blockIdx.y * 64, n0 = blockIdx.x * 128;
    const int z = blockIdx.z;
    const int kbeg = z * kchunk;
    const int kend = min(K, kbeg + kchunk);
    const int nsteps = (kend - kbeg + 15) >> 4;

    // load assignments
    const int aq = tid & 3, am = tid >> 2;          // A: q*4 k-offset, row am
    const int bq = tid & 3, bn = tid >> 2;          // B TRANSB: rows bn, bn+64
    float4 ra, rb0, rb1;

    ull acc0[8], acc1[8];
    #pragma unroll
    for (int n = 0; n < 8; n++) { acc0[n] = 0ull; acc1[n] = 0ull; }

    // ---- LDG for step k0 ----
    #define LDG_STEP(k0)                                                          \
    {                                                                             \
        int gk = (k0) + aq * 4;                                                   \
        int gm = m0 + am;                                                         \
        ra = make_float4(0.f, 0.f, 0.f, 0.f);                                     \
        if (gm < M && gk < kend) ra = *(const float4*)(A + (size_t)gm * K + gk);  \
        if (TRANSB) {                                                             \
            int gkb = (k0) + bq * 4;                                              \
            int gn0 = n0 + bn, gn1 = n0 + bn + 64;                                \
            rb0 = make_float4(0.f, 0.f, 0.f, 0.f);                                \
            rb1 = make_float4(0.f, 0.f, 0.f, 0.f);                                \
            if (gn0 < N && gkb < kend) rb0 = *(const float4*)(B + (size_t)gn0 * K + gkb); \
            if (gn1 < N && gkb < kend) rb1 = *(const float4*)(B + (size_t)gn1 * K + gkb); \
        } else {                                                                  \
            int kk0 = tid >> 5, kk1 = (tid + 256) >> 5;                           \
            int n4 = (tid & 31) * 4;                                              \
            int gka = (k0) + kk0, gkb2 = (k0) + kk1;                              \
            rb0 = make_float4(0.f, 0.f, 0.f, 0.f);                                \
            rb1 = make_float4(0.f, 0.f, 0.f, 0.f);                                \
            if (gka < kend && n0 + n4 + 3 < N) rb0 = *(const float4*)(B + (size_t)gka * N + n0 + n4); \
            if (gkb2 < kend && n0 + n4 + 3 < N) rb1 = *(const float4*)(B + (size_t)gkb2 * N + n0 + n4); \
        }                                                                         \
    }

    #define STS_STEP(bf)                                                          \
    {                                                                             \
        As[bf][aq * 4 + 0][am] = ra.x;                                            \
        As[bf][aq * 4 + 1][am] = ra.y;                                            \
        As[bf][aq * 4 + 2][am] = ra.z;                                            \
        As[bf][aq * 4 + 3][am] = ra.w;                                            \
        if (TRANSB) {                                                             \
            Bs[bf][bq * 4 + 0][bn] = rb0.x;                                       \
            Bs[bf][bq * 4 + 1][bn] = rb0.y;                                       \
            Bs[bf][bq * 4 + 2][bn] = rb0.z;                                       \
            Bs[bf][bq * 4 + 3][bn] = rb0.w;                                       \
            Bs[bf][bq * 4 + 0][bn + 64] = rb1.x;                                  \
            Bs[bf][bq * 4 + 1][bn + 64] = rb1.y;                                  \
            Bs[bf][bq * 4 + 2][bn + 64] = rb1.z;                                  \
            Bs[bf][bq * 4 + 3][bn + 64] = rb1.w;                                  \
        } else {                                                                  \
            int kk0 = tid >> 5, kk1 = (tid + 256) >> 5;                           \
            int n4 = (tid & 31) * 4;                                              \
            *(float4*)&Bs[bf][kk0][n4] = rb0;                                     \
            *(float4*)&Bs[bf][kk1][n4] = rb1;                                     \
        }                                                                         \
    }

    LDG_STEP(kbeg);
    STS_STEP(0);
    __syncthreads();

    int buf = 0;
    for (int s = 0; s < nsteps; s++) {
        bool more = (s + 1 < nsteps);
        if (more) { LDG_STEP(kbeg + (s + 1) * 16); }
        #pragma unroll
        for (int kk = 0; kk < 16; kk++) {
            float4 av = *(const float4*)&As[buf][kk][ty * 4];
            float4 b0 = *(const float4*)&Bs[buf][kk][tx * 8];
            float4 b1 = *(const float4*)&Bs[buf][kk][tx * 8 + 4];
            ull a01 = pack2(av.x, av.y);
            ull a23 = pack2(av.z, av.w);
            ull d;
            d = pack2(b0.x, b0.x); acc0[0] = ffma2(a01, d, acc0[0]); acc1[0] = ffma2(a23, d, acc1[0]);
            d = pack2(b0.y, b0.y); acc0[1] = ffma2(a01, d, acc0[1]); acc1[1] = ffma2(a23, d, acc1[1]);
            d = pack2(b0.z, b0.z); acc0[2] = ffma2(a01, d, acc0[2]); acc1[2] = ffma2(a23, d, acc1[2]);
            d = pack2(b0.w, b0.w); acc0[3] = ffma2(a01, d, acc0[3]); acc1[3] = ffma2(a23, d, acc1[3]);
            d = pack2(b1.x, b1.x); acc0[4] = ffma2(a01, d, acc0[4]); acc1[4] = ffma2(a23, d, acc1[4]);
            d = pack2(b1.y, b1.y); acc0[5] = ffma2(a01, d, acc0[5]); acc1[5] = ffma2(a23, d, acc1[5]);
            d = pack2(b1.z, b1.z); acc0[6] = ffma2(a01, d, acc0[6]); acc1[6] = ffma2(a23, d, acc1[6]);
            d = pack2(b1.w, b1.w); acc0[7] = ffma2(a01, d, acc0[7]); acc1[7] = ffma2(a23, d, acc1[7]);
        }
        if (more) {
            STS_STEP(buf ^ 1);
            __syncthreads();
            buf ^= 1;
        }
    }

    // epilogue
    float cv[4][8];
    #pragma unroll
    for (int n = 0; n < 8; n++) {
        unpack2(acc0[n], cv[0][n], cv[1][n]);
        unpack2(acc1[n], cv[2][n], cv[3][n]);
    }
    const bool direct = (gridDim.z == 1);
    float* op = direct ? dst : (slab + (size_t)z * M * N);
    int gnb = n0 + tx * 8;
    #pragma unroll
    for (int r = 0; r < 4; r++) {
        int gm = m0 + ty * 4 + r;
        if (gm >= M) continue;
        #pragma unroll
        for (int h = 0; h < 2; h++) {
            int gn = gnb + h * 4;
            if (gn < N) {
                float4 v = make_float4(cv[r][h * 4 + 0], cv[r][h * 4 + 1],
                                       cv[r][h * 4 + 2], cv[r][h * 4 + 3]);
                if (direct && bias) {
                    v.x += bias[gn]; v.y += bias[gn + 1];
                    v.z += bias[gn + 2]; v.w += bias[gn + 3];
                }
                *(float4*)&op[(size_t)gm * N + gn] = v;
            }
        }
    }
    #undef LDG_STEP
    #undef STS_STEP
}

// vectorized split-K reduce: dst = sum_z slab[z] (+bias)
__global__ void k_reduce(const float4* __restrict__ slab, const float* __restrict__ bias,
                         float4* __restrict__ dst, int total4, int n4, int splits) {
    int idx = blockIdx.x * blockDim.x + threadIdx.x;
    if (idx >= total4) return;
    float4 s = slab[idx];
    for (int zz = 1; zz < splits; zz++) {
        float4 t = slab[(size_t)zz * total4 + idx];
        s.x += t.x; s.y += t.y; s.z += t.z; s.w += t.w;
    }
    if (bias) {
        int n = (idx % n4) * 4;
        s.x += bias[n]; s.y += bias[n + 1]; s.z += bias[n + 2]; s.w += bias[n + 3];
    }
    dst[idx] = s;
}

// pooled[b][c][k] = sum_s img[b][k*100+s] * cls[c][k*100+s]
__global__ void k_pooled() {
    __shared__ float simg[32][101];
    __shared__ float scls[CC][101];
    int k = blockIdx.x % KK;
    int b0 = (blockIdx.x / KK) * 32;
    int tid = threadIdx.x;
    for (int idx = tid; idx < 32 * SS; idx += 256) {
        int r = idx / SS, s = idx % SS;
        simg[r][s] = g_img[(size_t)(b0 + r) * JJ + k * SS + s];
    }
    for (int idx = tid; idx < CC * SS; idx += 256) {
        int c = idx / SS, s = idx % SS;
        scls[c][s] = g_cls[(size_t)c * JJ + k * SS + s];
    }
    __syncthreads();
    for (int o = tid; o < 32 * CC; o += 256) {
        int lb = o / CC, c = o % CC;
        float acc = 0.f;
        #pragma unroll 4
        for (int s = 0; s < SS; s++) acc = fmaf(simg[lb][s], scls[c][s], acc);
        g_pooled[(size_t)(b0 + lb) * (CC * KK) + c * KK + k] = acc;
    }
}

__global__ void k_outgemm(const float* __restrict__ Wml, const float* __restrict__ bml,
                          float* __restrict__ out) {
    int w = (blockIdx.x * blockDim.x + threadIdx.x) >> 5;
    int lane = threadIdx.x & 31;
    if (w >= BB * CC) return;
    int b = w / CC, c = w % CC;
    const float* pp = g_pooled + (size_t)b * (CC * KK);
    const float* wp = Wml + (size_t)c * (CC * KK);
    float s = 0.f;
    #pragma unroll 8
    for (int t = lane; t < CC * KK; t += 32) s = fmaf(pp[t], wp[t], s);
    #pragma unroll
    for (int o = 16; o; o >>= 1) s += __shfl_xor_sync(0xffffffffu, s, o);
    if (lane == 0) out[w] = s + bml[c];
}

// ---------------- launcher ----------------

static inline float* symaddr(const void* sym) {
    void* p = nullptr;
    cudaGetSymbolAddress(&p, sym);
    return (float*)p;
}

extern "C" void kernel_launch(void* const* d_in, const int* in_sizes, int n_in,
                              void* d_out, int out_size) {
    const float* feature = (const float*)d_in[0];
    const float* inp     = (const float*)d_in[1];
    const float* Wb1     = (const float*)d_in[2];
    const float* bb1     = (const float*)d_in[3];
    const float* Wb2     = (const float*)d_in[4];
    const float* bb2     = (const float*)d_in[5];
    const float* Wg1     = (const float*)d_in[6];
    const float* Wg2     = (const float*)d_in[7];
    const float* Wimg    = (const float*)d_in[8];
    const float* bimg    = (const float*)d_in[9];
    const float* Wcls    = (const float*)d_in[10];
    const float* bcls    = (const float*)d_in[11];
    const float* Wml     = (const float*)d_in[12];
    const float* bml     = (const float*)d_in[13];
    float* out = (float*)d_out;

    float* p_t1   = symaddr(g_t1);
    float* p_y    = symaddr(g_y);
    float* p_img  = symaddr(g_img);
    float* p_cls  = symaddr(g_cls);
    float* p_h    = symaddr(g_h);
    float* p_x    = symaddr(g_x);
    float* p_feat = symaddr(g_feat);
    float* p_slab = symaddr(g_slab);

    // 1) maxpool
    k_maxpool<<<(BB * FDIM * 32 + 255) / 256, 256>>>(feature);
    // 2) sigmoid branches
    k_b1b2<<<(2 * DE1 * CC + 255) / 256, 256>>>(Wb1, bb1, Wb2, bb2, inp);
    // 3) A_wave + fused normalization/loss
    k_awave<<<(CC * CC * 32 + 255) / 256, 256>>>();
    k_norm<<<1, 1024>>>(out_size > BB * CC ? out + BB * CC : nullptr);
    // 4) t1 = inp @ Wg1  [80,1024], K=300, direct
    gemm_pl<false><<<dim3(8, 2, 1), 256>>>(inp, Wg1, p_slab, p_t1, nullptr, CC, DE1, DE, DE);
    // 5) h = leaky(Ahat @ t1)
    k_gcn1<<<(CC * DE1 + 255) / 256, 256>>>();
    // 6) y = h @ Wg2  [80,2048], K=1024, split 4
    gemm_pl<false><<<dim3(16, 2, 4), 256>>>(p_h, Wg2, p_slab, nullptr, nullptr, CC, FDIM, DE1, 256);
    k_reduce<<<(CC * FDIM / 4 + 255) / 256, 256>>>((const float4*)p_slab, nullptr,
                                                   (float4*)p_y, CC * FDIM / 4, FDIM / 4, 4);
    // 7) x = Ahat @ y
    k_gcn2<<<(CC * FDIM + 255) / 256, 256>>>();
    // 8) img = feat @ Wimg^T + bimg  [64,4000], K=2048, split 8
    gemm_pl<true><<<dim3(32, 1, 8), 256>>>(p_feat, Wimg, p_slab, nullptr, nullptr, BB, JJ, FDIM, 256);
    k_reduce<<<(BB * JJ / 4 + 255) / 256, 256>>>((const float4*)p_slab, bimg,
                                                 (float4*)p_img, BB * JJ / 4, JJ / 4, 8);
    // 9) cls = x @ Wcls^T + bcls  [80,4000], K=2048, split 4
    gemm_pl<true><<<dim3(32, 2, 4), 256>>>(p_x, Wcls, p_slab, nullptr, nullptr, CC, JJ, FDIM, 512);
    k_reduce<<<(CC * JJ / 4 + 255) / 256, 256>>>((const float4*)p_slab, bcls,
                                                 (float4*)p_cls, CC * JJ / 4, JJ / 4, 4);
    // 10) pooled
    k_pooled<<<KK * 2, 256>>>();
    // 11) out
    k_outgemm<<<(BB * CC * 32 + 255) / 256, 256>>>(Wml, bml, out);
}